// round 8
// baseline (speedup 1.0000x reference)
#include <cuda_runtime.h>

#define NN 2048
#define DD 8
#define HH 64
#define KB 128           // histogram buckets
#define NTH 1024

// Per-h F-table (float4[33]): 32 float4 of F edges + {F[128]=0, lo, invD, totS}
__device__ float4 g_F[HH * 33];
__device__ unsigned g_cnt = 0;            // monotonic grid-barrier ticket counter

// Order-preserving float <-> uint map (for atomicMin/Max on floats)
__device__ __forceinline__ unsigned fenc(float f) {
    unsigned u = __float_as_uint(f);
    return (u & 0x80000000u) ? ~u : (u | 0x80000000u);
}
__device__ __forceinline__ float fdec(unsigned e) {
    return (e & 0x80000000u) ? __uint_as_float(e ^ 0x80000000u)
                             : __uint_as_float(~e);
}

// ---------------------------------------------------------------------------
// One kernel, grid 64 x 1024 (all CTAs co-resident).
// Phase A (h = blockIdx.x): x2 projections -> 128-bin exact histogram ->
//   warp-0 register scan -> 528B F-table to g_F.  All phase-B constants are
//   prefetched into smem here (they don't depend on other CTAs).
// Grid barrier (monotonic ticket; graph-replay safe).
// Phase B (i-rows [32b,32b+32)): stage all 64 F-tables (33KB) in smem,
//   recompute x1/x2 per (i,h) from smem W1^T, O(1) lerp query, warp-shuffle
//   reduce over h, store out directly.
// ---------------------------------------------------------------------------
__global__ void __launch_bounds__(NTH) k_fused(const float* __restrict__ msg,
                                               const float* __restrict__ W1,
                                               const float* __restrict__ b1,
                                               const float* __restrict__ W2,
                                               const float* __restrict__ b2,
                                               float* __restrict__ out) {
    const int h = blockIdx.x;
    __shared__ __align__(16) float Ft[HH * 132];   // 33.8 KB (all F tables)
    __shared__ __align__(16) float W1t[16 * 64];   // transposed [k][h]
    __shared__ __align__(16) float W2s[DD * HH];
    __shared__ __align__(16) float msgs[32 * 8];   // own 32 message rows
    __shared__ __align__(16) float cnt[KB];
    __shared__ __align__(16) float sum[KB];
    __shared__ float b1s[HH];
    __shared__ float b2s[DD];
    __shared__ unsigned lo_u, hi_u;

    const int t = threadIdx.x;
    const int lane = t & 31;
    const int wid = t >> 5;

    // ---- Phase A prefetches (also hide msg latency behind B0) ----
    const float4* m0p = reinterpret_cast<const float4*>(msg + t * 8);
    const float4* m1p = reinterpret_cast<const float4*>(msg + (t + NTH) * 8);
    float4 a0 = m0p[0], a1 = m0p[1];
    float4 c0 = m1p[0], c1 = m1p[1];

    { int hh = t >> 4, k = t & 15; W1t[k * 64 + hh] = W1[t]; }  // all 1024
    if (t < KB) { cnt[t] = 0.0f; sum[t] = 0.0f; }
    if (t < 64) b1s[t] = b1[t];
    if (t < 512) W2s[t] = W2[t];
    if (t < 8) b2s[t] = b2[t];
    if (t < 64)
        reinterpret_cast<float4*>(msgs)[t] =
            reinterpret_cast<const float4*>(msg)[blockIdx.x * 64 + t];
    if (t == NTH - 1) { lo_u = 0xFFFFFFFFu; hi_u = 0u; }
    __syncthreads();  // B0

    // x2 projections for rows t, t+1024 (weights via LDS broadcast from W1t)
    float x2_0 = 0.0f, x2_1 = 0.0f;
#pragma unroll
    for (int k = 0; k < 8; k++) {
        float wk = W1t[(k + 8) * 64 + h];
        float m0k = (k < 4) ? ((k == 0) ? a0.x : (k == 1) ? a0.y : (k == 2) ? a0.z : a0.w)
                            : ((k == 4) ? a1.x : (k == 5) ? a1.y : (k == 6) ? a1.z : a1.w);
        float m1k = (k < 4) ? ((k == 0) ? c0.x : (k == 1) ? c0.y : (k == 2) ? c0.z : c0.w)
                            : ((k == 4) ? c1.x : (k == 5) ? c1.y : (k == 6) ? c1.z : c1.w);
        x2_0 += m0k * wk;
        x2_1 += m1k * wk;
    }

    float mn = fminf(x2_0, x2_1), mx = fmaxf(x2_0, x2_1);
#pragma unroll
    for (int o = 16; o >= 1; o >>= 1) {
        mn = fminf(mn, __shfl_xor_sync(0xffffffffu, mn, o));
        mx = fmaxf(mx, __shfl_xor_sync(0xffffffffu, mx, o));
    }
    if (lane == 0) {
        atomicMin(&lo_u, fenc(mn));
        atomicMax(&hi_u, fenc(mx));
    }
    __syncthreads();  // B1

    const float lo = fdec(lo_u), hi = fdec(hi_u);
    const float range = fmaxf(hi - lo, 1e-30f);
    const float invD = (float)KB / range;
    const float Delta = range / (float)KB;

    int bi0 = (int)fminf(fmaxf((x2_0 - lo) * invD, 0.0f), (float)(KB - 1));
    int bi1 = (int)fminf(fmaxf((x2_1 - lo) * invD, 0.0f), (float)(KB - 1));
    atomicAdd(&cnt[bi0], 1.0f); atomicAdd(&sum[bi0], x2_0);
    atomicAdd(&cnt[bi1], 1.0f); atomicAdd(&sum[bi1], x2_1);
    __syncthreads();  // B2

    // warp 0: register scan of 128 buckets (4/lane) -> g_F[h]
    if (wid == 0) {
        float4 cc = reinterpret_cast<const float4*>(cnt)[lane];
        float4 ss = reinterpret_cast<const float4*>(sum)[lane];
        float ctot = cc.x + cc.y + cc.z + cc.w;
        float stot = ss.x + ss.y + ss.z + ss.w;
        float cI = ctot, sI = stot;
#pragma unroll
        for (int o = 1; o < 32; o <<= 1) {
            float nc = __shfl_up_sync(0xffffffffu, cI, o);
            float ns = __shfl_up_sync(0xffffffffu, sI, o);
            if (lane >= o) { cI += nc; sI += ns; }
        }
        const float totS = __shfl_sync(0xffffffffu, sI, 31);
        float pc = cI - ctot, ps = sI - stot;  // exclusive prefix of this chunk
        float thr = lo + (float)(4 * lane) * Delta;
        float F0 = (totS - ps) - thr * (2048.0f - pc); pc += cc.x; ps += ss.x; thr += Delta;
        float F1 = (totS - ps) - thr * (2048.0f - pc); pc += cc.y; ps += ss.y; thr += Delta;
        float F2 = (totS - ps) - thr * (2048.0f - pc); pc += cc.z; ps += ss.z; thr += Delta;
        float F3 = (totS - ps) - thr * (2048.0f - pc);
        g_F[h * 33 + lane] = make_float4(F0, F1, F2, F3);
        if (lane == 31) g_F[h * 33 + 32] = make_float4(0.0f, lo, invD, totS);
    }

    // ---- grid barrier (monotonic ticket; all 64 CTAs co-resident) ----
    __syncthreads();   // warp-0 g_F stores ordered before the fence below
    if (t == 0) {
        __threadfence();                                  // publish g_F
        unsigned ticket = atomicAdd(&g_cnt, 1u) + 1u;
        unsigned target = ((ticket - 1u) | 63u) + 1u;     // next multiple of 64
        unsigned v;
        do {
            asm volatile("ld.global.acquire.gpu.u32 %0, [%1];"
                         : "=r"(v) : "l"(&g_cnt));
        } while (v < target);
    }
    __syncthreads();   // release to whole block

    // ---- Phase B: stage all F tables, emit out rows [32*blk, 32*blk+32) ----
    float4* Ft4 = reinterpret_cast<float4*>(Ft);
    for (int idx = t; idx < HH * 33; idx += NTH) Ft4[idx] = g_F[idx];
    __syncthreads();  // B3

    // warp wid owns i = 32*blk + wid; lane owns h = lane and lane+32
    float m[8];
#pragma unroll
    for (int k = 0; k < 8; k++) m[k] = msgs[wid * 8 + k];

    float acc[DD];
#pragma unroll
    for (int d = 0; d < DD; d++) acc[d] = 0.0f;

#pragma unroll
    for (int r = 0; r < 2; r++) {
        const int hh = lane + r * 32;
        float x1 = 0.0f, x2 = 0.0f;
#pragma unroll
        for (int k = 0; k < 8; k++) {
            x1 += m[k] * W1t[k * 64 + hh];          // bank = hh%32 = lane: conflict-free
            x2 += m[k] * W1t[(k + 8) * 64 + hh];
        }
        float a = x1 + b1s[hh];
        float thr = -a;
        const float* F = &Ft[hh * 132];
        float4 meta = *reinterpret_cast<const float4*>(F + 128);  // {0, lo, invD, totS}
        float u = (thr - meta.y) * meta.z;
        float f;
        if (u < 0.0f) {
            f = meta.w - thr * 2048.0f;             // exact: all elements active
        } else if (u >= (float)KB) {
            f = 0.0f;                                // exact: none active
        } else {
            int bb = (int)u;
            float fr = u - (float)bb;
            float f0 = F[bb], f1 = F[bb + 1];
            f = f0 + fr * (f1 - f0);
        }
        float T = f - fmaxf(a + x2, 0.0f);
#pragma unroll
        for (int d = 0; d < DD; d++) acc[d] += T * W2s[d * 64 + hh];
    }

#pragma unroll
    for (int d = 0; d < DD; d++) {
#pragma unroll
        for (int o = 16; o >= 1; o >>= 1)
            acc[d] += __shfl_xor_sync(0xffffffffu, acc[d], o);
    }
    const float inv = 1.0f / (float)(NN - 1);
#pragma unroll
    for (int d = 0; d < DD; d++)
        if (lane == d) out[(blockIdx.x * 32 + wid) * DD + d] = acc[d] * inv + b2s[d];
}

// ---------------------------------------------------------------------------
extern "C" void kernel_launch(void* const* d_in, const int* in_sizes, int n_in,
                              void* d_out, int out_size) {
    // Identify inputs by element count (all distinct): robust to ordering.
    const float* msg = nullptr;  // 2048*8   = 16384
    const float* W1  = nullptr;  // 64*16    = 1024
    const float* b1  = nullptr;  // 64
    const float* W2  = nullptr;  // 8*64     = 512
    const float* b2  = nullptr;  // 8
    for (int k = 0; k < n_in; k++) {
        switch (in_sizes[k]) {
            case 16384: msg = (const float*)d_in[k]; break;
            case 1024:  W1  = (const float*)d_in[k]; break;
            case 64:    b1  = (const float*)d_in[k]; break;
            case 512:   W2  = (const float*)d_in[k]; break;
            case 8:     b2  = (const float*)d_in[k]; break;
            default: break;
        }
    }
    float* out = (float*)d_out;

    k_fused<<<HH, NTH>>>(msg, W1, b1, W2, b2, out);
}

// round 9
// speedup vs baseline: 1.3692x; 1.3692x over previous
#include <cuda_runtime.h>

#define NN 2048
#define DD 8
#define HH 64
#define KB 512           // histogram buckets
#define NTH 1024         // threads per block

// Scratch (no allocation allowed in kernel_launch).
__device__ float g_T[HH * NN];            // (S - D)[h][i]
__device__ unsigned g_cnt = 0;            // monotonic grid-barrier ticket counter

// Order-preserving float <-> uint map (for atomicMin/Max on floats)
__device__ __forceinline__ unsigned fenc(float f) {
    unsigned u = __float_as_uint(f);
    return (u & 0x80000000u) ? ~u : (u | 0x80000000u);
}
__device__ __forceinline__ float fdec(unsigned e) {
    return (e & 0x80000000u) ? __uint_as_float(e ^ 0x80000000u)
                             : __uint_as_float(~e);
}

// ---------------------------------------------------------------------------
// One fused kernel: block = one h (grid 64, all co-resident).
// Phase A: projections -> exact histogram CDF table F (512 bins) -> per-i
//          relu-sum queries -> g_T[h][:].   (4 block barriers)
// Grid barrier (monotonic ticket + nanosleep backoff; graph-replay safe).
// Phase B: block b emits out rows [32b, 32b+32) from coalesced g_T reads.
// ---------------------------------------------------------------------------
__global__ void __launch_bounds__(NTH) k_fused(const float* __restrict__ msg,
                                               const float* __restrict__ W1,
                                               const float* __restrict__ b1,
                                               const float* __restrict__ W2,
                                               const float* __restrict__ b2,
                                               float* __restrict__ out) {
    const int h = blockIdx.x;
    __shared__ __align__(16) float w[16];
    __shared__ __align__(16) float w2s[DD * HH];
    __shared__ __align__(16) float b2s[DD];
    __shared__ __align__(16) float cnt[KB];
    __shared__ __align__(16) float sum[KB];
    __shared__ __align__(16) float Farr[KB + 1];
    __shared__ __align__(16) float red[8][32][DD];
    __shared__ unsigned sh_lo_u, sh_hi_u;
    __shared__ float sh_totS;

    const int t = threadIdx.x;
    const int lane = t & 31;
    const int wid = t >> 5;

    // Prefetch message rows (independent of smem) to hide latency behind B0.
    const int j0 = t, j1 = t + NTH;
    const float4* m0p = reinterpret_cast<const float4*>(msg + j0 * 8);
    const float4* m1p = reinterpret_cast<const float4*>(msg + (j1) * 8);
    float4 a0 = m0p[0], a1 = m0p[1];
    float4 c0 = m1p[0], c1 = m1p[1];

    if (t < 16) w[t] = W1[h * 16 + t];
    if (t >= 32 && t < 32 + DD * HH) w2s[t - 32] = W2[t - 32];
    if (t >= 544 && t < 544 + DD) b2s[t - 544] = b2[t - 544];
    if (t == 1023) { sh_lo_u = 0xFFFFFFFFu; sh_hi_u = 0u; }
    if (t < KB) { cnt[t] = 0.0f; sum[t] = 0.0f; }
    const float b1h = __ldg(&b1[h]);
    __syncthreads();  // B0: w ready, hist zeroed, lo/hi init

    float x1_0 = a0.x*w[0]+a0.y*w[1]+a0.z*w[2]+a0.w*w[3]
               + a1.x*w[4]+a1.y*w[5]+a1.z*w[6]+a1.w*w[7];
    float x2_0 = a0.x*w[8]+a0.y*w[9]+a0.z*w[10]+a0.w*w[11]
               + a1.x*w[12]+a1.y*w[13]+a1.z*w[14]+a1.w*w[15];
    float x1_1 = c0.x*w[0]+c0.y*w[1]+c0.z*w[2]+c0.w*w[3]
               + c1.x*w[4]+c1.y*w[5]+c1.z*w[6]+c1.w*w[7];
    float x2_1 = c0.x*w[8]+c0.y*w[9]+c0.z*w[10]+c0.w*w[11]
               + c1.x*w[12]+c1.y*w[13]+c1.z*w[14]+c1.w*w[15];

    // warp min/max of x2, one atomic per warp
    float mn = fminf(x2_0, x2_1), mx = fmaxf(x2_0, x2_1);
#pragma unroll
    for (int o = 16; o >= 1; o >>= 1) {
        mn = fminf(mn, __shfl_xor_sync(0xffffffffu, mn, o));
        mx = fmaxf(mx, __shfl_xor_sync(0xffffffffu, mx, o));
    }
    if (lane == 0) {
        atomicMin(&sh_lo_u, fenc(mn));
        atomicMax(&sh_hi_u, fenc(mx));
    }
    __syncthreads();  // B1: lo/hi final

    const float lo = fdec(sh_lo_u), hi = fdec(sh_hi_u);
    const float range = fmaxf(hi - lo, 1e-30f);
    const float invD = (float)KB / range;
    const float Delta = range / (float)KB;

    // histogram (smem float atomics)
    int bi0 = (int)fminf(fmaxf((x2_0 - lo) * invD, 0.0f), (float)(KB - 1));
    int bi1 = (int)fminf(fmaxf((x2_1 - lo) * invD, 0.0f), (float)(KB - 1));
    atomicAdd(&cnt[bi0], 1.0f); atomicAdd(&sum[bi0], x2_0);
    atomicAdd(&cnt[bi1], 1.0f); atomicAdd(&sum[bi1], x2_1);
    __syncthreads();  // B2: hist final

    // warp 0: register scan of 512 buckets (16/lane) -> Farr
    if (wid == 0) {
        float c[16], s[16];
        const float4* c4 = reinterpret_cast<const float4*>(cnt) + lane * 4;
        const float4* s4 = reinterpret_cast<const float4*>(sum) + lane * 4;
#pragma unroll
        for (int q = 0; q < 4; q++) {
            float4 cc = c4[q], ss = s4[q];
            c[q*4+0]=cc.x; c[q*4+1]=cc.y; c[q*4+2]=cc.z; c[q*4+3]=cc.w;
            s[q*4+0]=ss.x; s[q*4+1]=ss.y; s[q*4+2]=ss.z; s[q*4+3]=ss.w;
        }
        float ctot = 0.0f, stot = 0.0f;
#pragma unroll
        for (int k = 0; k < 16; k++) { ctot += c[k]; stot += s[k]; }
        float cI = ctot, sI = stot;
#pragma unroll
        for (int o = 1; o < 32; o <<= 1) {
            float nc = __shfl_up_sync(0xffffffffu, cI, o);
            float ns = __shfl_up_sync(0xffffffffu, sI, o);
            if (lane >= o) { cI += nc; sI += ns; }
        }
        const float totS = __shfl_sync(0xffffffffu, sI, 31);
        if (lane == 31) sh_totS = totS;
        float pc = cI - ctot, ps = sI - stot;   // exclusive prefix before chunk
        float Fv[16];
#pragma unroll
        for (int k = 0; k < 16; k++) {
            float thr = lo + (float)(16 * lane + k) * Delta;
            Fv[k] = (totS - ps) - thr * ((float)NN - pc);
            pc += c[k]; ps += s[k];
        }
        float4* F4 = reinterpret_cast<float4*>(Farr) + lane * 4;
#pragma unroll
        for (int q = 0; q < 4; q++) {
            F4[q] = make_float4(Fv[q*4+0], Fv[q*4+1], Fv[q*4+2], Fv[q*4+3]);
        }
        if (lane == 31) Farr[KB] = 0.0f;
    }
    __syncthreads();  // B3: F ready

    const float totS = sh_totS;

    // queries -> g_T[h][:]
#pragma unroll
    for (int r = 0; r < 2; r++) {
        float x1v = r ? x1_1 : x1_0;
        float x2v = r ? x2_1 : x2_0;
        int j = r ? j1 : j0;
        float a = x1v + b1h;
        float thr = -a;
        float f;
        if (thr < lo) {
            f = totS - thr * (float)NN;           // exact: all elements active
        } else if (thr >= hi) {
            f = 0.0f;                              // exact: none active
        } else {
            float u = (thr - lo) * invD;
            int b = (int)u; b = b > KB - 1 ? KB - 1 : b;
            float frac = u - (float)b;
            float f0 = Farr[b], f1 = Farr[b + 1];
            f = f0 + frac * (f1 - f0);
        }
        float Dg = fmaxf(a + x2v, 0.0f);
        g_T[h * NN + j] = f - Dg;
    }

    // ---- grid barrier: monotonic ticket + nanosleep backoff ----
    __syncthreads();   // all g_T stores issued
    if (t == 0) {
        __threadfence();                                  // publish g_T
        unsigned ticket = atomicAdd(&g_cnt, 1u) + 1u;
        unsigned target = ((ticket - 1u) | 63u) + 1u;     // next multiple of 64
        unsigned v;
        int polls = 0;
        for (;;) {
            asm volatile("ld.global.acquire.gpu.u32 %0, [%1];"
                         : "=r"(v) : "l"(&g_cnt));
            if (v >= target) break;
            if (++polls > 2) __nanosleep(64);             // backoff: unload the LTS slice
        }
    }
    __syncthreads();   // release to whole block

    // ---- Phase B: out rows [32*blk, 32*blk+32) ----
    const int base_i = blockIdx.x * 32;
    if (t < 256) {
        float acc[DD];
#pragma unroll
        for (int d = 0; d < DD; d++) acc[d] = 0.0f;
#pragma unroll
        for (int k = 0; k < 8; k++) {
            const int hh = wid * 8 + k;
            float v = g_T[hh * NN + base_i + lane];
#pragma unroll
            for (int d = 0; d < DD; d++) acc[d] += v * w2s[d * HH + hh];
        }
#pragma unroll
        for (int d = 0; d < DD; d++) red[wid][lane][d] = acc[d];
    }
    __syncthreads();

    if (t < 256) {
        const int il = t >> 3, d = t & 7;
        float s = 0.0f;
#pragma unroll
        for (int wdx = 0; wdx < 8; wdx++) s += red[wdx][il][d];
        out[base_i * DD + t] = s * (1.0f / (float)(NN - 1)) + b2s[d];
    }
}

// ---------------------------------------------------------------------------
extern "C" void kernel_launch(void* const* d_in, const int* in_sizes, int n_in,
                              void* d_out, int out_size) {
    // Identify inputs by element count (all distinct): robust to ordering.
    const float* msg = nullptr;  // 2048*8   = 16384
    const float* W1  = nullptr;  // 64*16    = 1024
    const float* b1  = nullptr;  // 64
    const float* W2  = nullptr;  // 8*64     = 512
    const float* b2  = nullptr;  // 8
    for (int k = 0; k < n_in; k++) {
        switch (in_sizes[k]) {
            case 16384: msg = (const float*)d_in[k]; break;
            case 1024:  W1  = (const float*)d_in[k]; break;
            case 64:    b1  = (const float*)d_in[k]; break;
            case 512:   W2  = (const float*)d_in[k]; break;
            case 8:     b2  = (const float*)d_in[k]; break;
            default: break;
        }
    }
    float* out = (float*)d_out;

    k_fused<<<HH, NTH>>>(msg, W1, b1, W2, b2, out);
}

// round 10
// speedup vs baseline: 1.3935x; 1.0178x over previous
#include <cuda_runtime.h>

#define NN 2048
#define DD 8
#define HH 64
#define KB 512           // histogram buckets
#define NTH 1024         // threads per block

// Scratch (no allocation allowed in kernel_launch).
__device__ float g_T[HH * NN];            // (S - D)[h][i]
// Distributed grid-barrier flags: one 128B line per CTA (single writer each).
__device__ unsigned g_flags[HH * 32];

// Order-preserving float <-> uint map (for atomicMin/Max on floats)
__device__ __forceinline__ unsigned fenc(float f) {
    unsigned u = __float_as_uint(f);
    return (u & 0x80000000u) ? ~u : (u | 0x80000000u);
}
__device__ __forceinline__ float fdec(unsigned e) {
    return (e & 0x80000000u) ? __uint_as_float(e ^ 0x80000000u)
                             : __uint_as_float(~e);
}

// ---------------------------------------------------------------------------
// One fused kernel: block = one h (grid 64, all co-resident).
// Phase A: projections -> exact histogram CDF table F (512 bins) -> per-i
//          relu-sum queries -> g_T[h][:].
// Grid barrier: distributed per-CTA flags (epoch = own flag + 1; monotonic,
//          graph-replay safe; no same-address atomic serialization).
// Phase B: block b emits out rows [32b, 32b+32) from coalesced g_T reads.
// ---------------------------------------------------------------------------
__global__ void __launch_bounds__(NTH) k_fused(const float* __restrict__ msg,
                                               const float* __restrict__ W1,
                                               const float* __restrict__ b1,
                                               const float* __restrict__ W2,
                                               const float* __restrict__ b2,
                                               float* __restrict__ out) {
    const int h = blockIdx.x;
    __shared__ __align__(16) float w[16];
    __shared__ __align__(16) float w2s[DD * HH];
    __shared__ __align__(16) float b2s[DD];
    __shared__ __align__(16) float cnt[KB];
    __shared__ __align__(16) float sum[KB];
    __shared__ __align__(16) float Farr[KB + 1];
    __shared__ __align__(16) float red[8][32][DD];
    __shared__ unsigned sh_lo_u, sh_hi_u;
    __shared__ float sh_totS;

    const int t = threadIdx.x;
    const int lane = t & 31;
    const int wid = t >> 5;

    // Prefetch message rows (independent of smem) to hide latency behind B0.
    const int j0 = t, j1 = t + NTH;
    const float4* m0p = reinterpret_cast<const float4*>(msg + j0 * 8);
    const float4* m1p = reinterpret_cast<const float4*>(msg + j1 * 8);
    float4 a0 = m0p[0], a1 = m0p[1];
    float4 c0 = m1p[0], c1 = m1p[1];

    if (t < 16) w[t] = W1[h * 16 + t];
    if (t >= 32 && t < 32 + DD * HH) w2s[t - 32] = W2[t - 32];
    if (t >= 544 && t < 544 + DD) b2s[t - 544] = b2[t - 544];
    if (t == 1023) { sh_lo_u = 0xFFFFFFFFu; sh_hi_u = 0u; }
    if (t < KB) { cnt[t] = 0.0f; sum[t] = 0.0f; }
    const float b1h = __ldg(&b1[h]);
    __syncthreads();  // B0: w ready, hist zeroed, lo/hi init

    float x1_0 = a0.x*w[0]+a0.y*w[1]+a0.z*w[2]+a0.w*w[3]
               + a1.x*w[4]+a1.y*w[5]+a1.z*w[6]+a1.w*w[7];
    float x2_0 = a0.x*w[8]+a0.y*w[9]+a0.z*w[10]+a0.w*w[11]
               + a1.x*w[12]+a1.y*w[13]+a1.z*w[14]+a1.w*w[15];
    float x1_1 = c0.x*w[0]+c0.y*w[1]+c0.z*w[2]+c0.w*w[3]
               + c1.x*w[4]+c1.y*w[5]+c1.z*w[6]+c1.w*w[7];
    float x2_1 = c0.x*w[8]+c0.y*w[9]+c0.z*w[10]+c0.w*w[11]
               + c1.x*w[12]+c1.y*w[13]+c1.z*w[14]+c1.w*w[15];

    // warp min/max of x2, one atomic per warp
    float mn = fminf(x2_0, x2_1), mx = fmaxf(x2_0, x2_1);
#pragma unroll
    for (int o = 16; o >= 1; o >>= 1) {
        mn = fminf(mn, __shfl_xor_sync(0xffffffffu, mn, o));
        mx = fmaxf(mx, __shfl_xor_sync(0xffffffffu, mx, o));
    }
    if (lane == 0) {
        atomicMin(&sh_lo_u, fenc(mn));
        atomicMax(&sh_hi_u, fenc(mx));
    }
    __syncthreads();  // B1: lo/hi final

    const float lo = fdec(sh_lo_u), hi = fdec(sh_hi_u);
    const float range = fmaxf(hi - lo, 1e-30f);
    const float invD = (float)KB / range;
    const float Delta = range / (float)KB;

    // histogram (smem float atomics)
    int bi0 = (int)fminf(fmaxf((x2_0 - lo) * invD, 0.0f), (float)(KB - 1));
    int bi1 = (int)fminf(fmaxf((x2_1 - lo) * invD, 0.0f), (float)(KB - 1));
    atomicAdd(&cnt[bi0], 1.0f); atomicAdd(&sum[bi0], x2_0);
    atomicAdd(&cnt[bi1], 1.0f); atomicAdd(&sum[bi1], x2_1);
    __syncthreads();  // B2: hist final

    // warp 0: register scan of 512 buckets (16/lane) -> Farr
    if (wid == 0) {
        float c[16], s[16];
        const float4* c4 = reinterpret_cast<const float4*>(cnt) + lane * 4;
        const float4* s4 = reinterpret_cast<const float4*>(sum) + lane * 4;
#pragma unroll
        for (int q = 0; q < 4; q++) {
            float4 cc = c4[q], ss = s4[q];
            c[q*4+0]=cc.x; c[q*4+1]=cc.y; c[q*4+2]=cc.z; c[q*4+3]=cc.w;
            s[q*4+0]=ss.x; s[q*4+1]=ss.y; s[q*4+2]=ss.z; s[q*4+3]=ss.w;
        }
        float ctot = 0.0f, stot = 0.0f;
#pragma unroll
        for (int k = 0; k < 16; k++) { ctot += c[k]; stot += s[k]; }
        float cI = ctot, sI = stot;
#pragma unroll
        for (int o = 1; o < 32; o <<= 1) {
            float nc = __shfl_up_sync(0xffffffffu, cI, o);
            float ns = __shfl_up_sync(0xffffffffu, sI, o);
            if (lane >= o) { cI += nc; sI += ns; }
        }
        const float totS = __shfl_sync(0xffffffffu, sI, 31);
        if (lane == 31) sh_totS = totS;
        float pc = cI - ctot, ps = sI - stot;   // exclusive prefix before chunk
        float Fv[16];
#pragma unroll
        for (int k = 0; k < 16; k++) {
            float thr = lo + (float)(16 * lane + k) * Delta;
            Fv[k] = (totS - ps) - thr * ((float)NN - pc);
            pc += c[k]; ps += s[k];
        }
        float4* F4 = reinterpret_cast<float4*>(Farr) + lane * 4;
#pragma unroll
        for (int q = 0; q < 4; q++) {
            F4[q] = make_float4(Fv[q*4+0], Fv[q*4+1], Fv[q*4+2], Fv[q*4+3]);
        }
        if (lane == 31) Farr[KB] = 0.0f;
    }
    __syncthreads();  // B3: F ready

    const float totS = sh_totS;

    // queries -> g_T[h][:]
#pragma unroll
    for (int r = 0; r < 2; r++) {
        float x1v = r ? x1_1 : x1_0;
        float x2v = r ? x2_1 : x2_0;
        int j = r ? j1 : j0;
        float a = x1v + b1h;
        float thr = -a;
        float f;
        if (thr < lo) {
            f = totS - thr * (float)NN;           // exact: all elements active
        } else if (thr >= hi) {
            f = 0.0f;                              // exact: none active
        } else {
            float u = (thr - lo) * invD;
            int b = (int)u; b = b > KB - 1 ? KB - 1 : b;
            float frac = u - (float)b;
            float f0 = Farr[b], f1 = Farr[b + 1];
            f = f0 + frac * (f1 - f0);
        }
        float Dg = fmaxf(a + x2v, 0.0f);
        g_T[h * NN + j] = f - Dg;
    }

    // ---- grid barrier: distributed per-CTA flags (no RMW serialization) ----
    __syncthreads();   // all g_T stores issued (CTA-visible to warp 0)
    if (wid == 0) {
        unsigned e = 0;
        if (lane == 0) {
            __threadfence();                              // publish g_T (gpu scope)
            e = g_flags[blockIdx.x * 32] + 1u;            // single writer: safe read
            asm volatile("st.global.relaxed.gpu.u32 [%0], %1;"
                         :: "l"(&g_flags[blockIdx.x * 32]), "r"(e) : "memory");
        }
        e = __shfl_sync(0xffffffffu, e, 0);
        const unsigned* f0 = &g_flags[lane * 32];
        const unsigned* f1 = &g_flags[(lane + 32) * 32];
        for (;;) {
            unsigned v0, v1;
            asm volatile("ld.global.acquire.gpu.u32 %0, [%1];" : "=r"(v0) : "l"(f0));
            asm volatile("ld.global.acquire.gpu.u32 %0, [%1];" : "=r"(v1) : "l"(f1));
            if (__all_sync(0xffffffffu, (v0 >= e) && (v1 >= e))) break;
            __nanosleep(32);
        }
    }
    __syncthreads();   // release to whole block

    // ---- Phase B: out rows [32*blk, 32*blk+32) ----
    const int base_i = blockIdx.x * 32;
    if (t < 256) {
        float acc[DD];
#pragma unroll
        for (int d = 0; d < DD; d++) acc[d] = 0.0f;
#pragma unroll
        for (int k = 0; k < 8; k++) {
            const int hh = wid * 8 + k;
            float v = g_T[hh * NN + base_i + lane];
#pragma unroll
            for (int d = 0; d < DD; d++) acc[d] += v * w2s[d * HH + hh];
        }
#pragma unroll
        for (int d = 0; d < DD; d++) red[wid][lane][d] = acc[d];
    }
    __syncthreads();

    if (t < 256) {
        const int il = t >> 3, d = t & 7;
        float s = 0.0f;
#pragma unroll
        for (int wdx = 0; wdx < 8; wdx++) s += red[wdx][il][d];
        out[base_i * DD + t] = s * (1.0f / (float)(NN - 1)) + b2s[d];
    }
}

// ---------------------------------------------------------------------------
extern "C" void kernel_launch(void* const* d_in, const int* in_sizes, int n_in,
                              void* d_out, int out_size) {
    // Identify inputs by element count (all distinct): robust to ordering.
    const float* msg = nullptr;  // 2048*8   = 16384
    const float* W1  = nullptr;  // 64*16    = 1024
    const float* b1  = nullptr;  // 64
    const float* W2  = nullptr;  // 8*64     = 512
    const float* b2  = nullptr;  // 8
    for (int k = 0; k < n_in; k++) {
        switch (in_sizes[k]) {
            case 16384: msg = (const float*)d_in[k]; break;
            case 1024:  W1  = (const float*)d_in[k]; break;
            case 64:    b1  = (const float*)d_in[k]; break;
            case 512:   W2  = (const float*)d_in[k]; break;
            case 8:     b2  = (const float*)d_in[k]; break;
            default: break;
        }
    }
    float* out = (float*)d_out;

    k_fused<<<HH, NTH>>>(msg, W1, b1, W2, b2, out);
}